// round 2
// baseline (speedup 1.0000x reference)
#include <cuda_runtime.h>

#define NBATCH 16
#define NPT    4096
#define NQ     1024
#define NSAMP  32
#define OUT1SZ (NBATCH*3*NQ)        // 49152
#define OUT2SZ (NBATCH*128*NQ)      // 2097152
#define MAXE   (NBATCH*NQ*NSAMP + 64)

__device__ int      g_fps[NBATCH*NQ];
__device__ unsigned g_ent[MAXE];
__device__ int      g_ecnt;
__device__ float    g_W0[67*64];    // [c][o] folded BN
__device__ float    g_B0[64];
__device__ float    g_W1[64*64];    // [c][o]
__device__ float    g_B1[64];
__device__ float    g_W2[64*128];   // [k][o]
__device__ float    g_B2[128];

// ---------------- prep: zero out2, fold BN into weights, reset counter ----
__global__ void prep_kernel(float* __restrict__ out2,
    const float* w0,const float* b0,const float* g0,const float* be0,const float* m0,const float* v0,
    const float* w1,const float* b1,const float* g1,const float* be1,const float* m1,const float* v1,
    const float* w2,const float* b2,const float* g2,const float* be2,const float* m2,const float* v2)
{
    int idx = blockIdx.x*blockDim.x + threadIdx.x;
    if (idx < OUT2SZ/4) ((float4*)out2)[idx] = make_float4(0.f,0.f,0.f,0.f);
    if (blockIdx.x == 0) {
        int t = threadIdx.x;
        if (t == 0) g_ecnt = 0;
        for (int i=t;i<67*64;i+=blockDim.x){int c=i>>6,o=i&63;float s=g0[o]*rsqrtf(v0[o]+1e-5f);g_W0[i]=w0[o*67+c]*s;}
        for (int i=t;i<64*64;i+=blockDim.x){int c=i>>6,o=i&63;float s=g1[o]*rsqrtf(v1[o]+1e-5f);g_W1[i]=w1[o*64+c]*s;}
        for (int i=t;i<64*128;i+=blockDim.x){int k=i>>7,o=i&127;float s=g2[o]*rsqrtf(v2[o]+1e-5f);g_W2[i]=w2[o*64+k]*s;}
        if (t<64){float s=g0[t]*rsqrtf(v0[t]+1e-5f);g_B0[t]=(b0[t]-m0[t])*s+be0[t];}
        if (t<64){float s=g1[t]*rsqrtf(v1[t]+1e-5f);g_B1[t]=(b1[t]-m1[t])*s+be1[t];}
        if (t<128){float s=g2[t]*rsqrtf(v2[t]+1e-5f);g_B2[t]=(b2[t]-m2[t])*s+be2[t];}
    }
}

// ---------------- FPS: one CTA per batch, points in registers ------------
// Each of 1024 threads owns 4 points. Centroid broadcast via 12B smem slot.
__global__ void __launch_bounds__(1024,1) fps_kernel(const float* __restrict__ xyz)
{
    __shared__ unsigned s_m[32];
    __shared__ unsigned s_i[32];
    __shared__ float    s_c[3];
    int b = blockIdx.x, t = threadIdx.x;
    const float* X = xyz + b*3*NPT;
    int base = t*4;
    float4 vx = *(const float4*)(X + base);
    float4 vy = *(const float4*)(X + NPT + base);
    float4 vz = *(const float4*)(X + 2*NPT + base);
    float px[4]={vx.x,vx.y,vx.z,vx.w};
    float py[4]={vy.x,vy.y,vy.z,vy.w};
    float pz[4]={vz.x,vz.y,vz.z,vz.w};
    float dd[4]={1e10f,1e10f,1e10f,1e10f};
    int lane = t & 31, wid = t >> 5;
    if (t == 0){ s_c[0]=px[0]; s_c[1]=py[0]; s_c[2]=pz[0]; }
    __syncthreads();
    int f = 0;
    for (int it=0; it<NQ; ++it) {
        if (t == 0) g_fps[b*NQ+it] = f;
        float cx = s_c[0], cy = s_c[1], cz = s_c[2];
        #pragma unroll
        for (int j=0;j<4;j++){
            float dx=px[j]-cx, dy=py[j]-cy, dz=pz[j]-cz;
            // match XLA: separately-rounded squares, left-assoc sum (no FMA contraction)
            float d = __fadd_rn(__fadd_rn(__fmul_rn(dx,dx),__fmul_rn(dy,dy)),__fmul_rn(dz,dz));
            dd[j] = fminf(dd[j], d);
        }
        float best = dd[0]; int bidx = base;
        #pragma unroll
        for (int j=1;j<4;j++) if (dd[j] > best){ best=dd[j]; bidx=base+j; }
        unsigned db   = __float_as_uint(best);        // >=0 floats: uint order == float order
        unsigned wmax = __reduce_max_sync(0xffffffffu, db);
        unsigned cand = (db==wmax) ? (unsigned)bidx : 0xffffffffu;
        unsigned widx = __reduce_min_sync(0xffffffffu, cand);   // first-index tie-break
        if (lane==0){ s_m[wid]=wmax; s_i[wid]=widx; }
        __syncthreads();
        unsigned vm = s_m[lane];
        unsigned vi = s_i[lane];
        unsigned bmax = __reduce_max_sync(0xffffffffu, vm);
        unsigned c2   = (vm==bmax) ? vi : 0xffffffffu;
        f = (int)__reduce_min_sync(0xffffffffu, c2);
        if (t == (f>>2)){
            int j = f & 3;
            s_c[0]=px[j]; s_c[1]=py[j]; s_c[2]=pz[j];
        }
        __syncthreads();   // protects s_c read next iter AND s_m/s_i overwrite
    }
}

// ---------------- gather new_xyz into d_out part 1 -----------------------
__global__ void gather_kernel(float* __restrict__ out1, const float* __restrict__ xyz){
    int idx = blockIdx.x*blockDim.x+threadIdx.x;
    if (idx >= OUT1SZ) return;
    int b = idx/3072, r = idx - b*3072, c = r>>10, s = r&1023;
    out1[idx] = xyz[(b*3+c)*NPT + g_fps[b*NQ+s]];
}

// ---------------- ball query: warp per query, ballot scan (global reads) --
__global__ void __launch_bounds__(256) bq_kernel(const float* __restrict__ xyz)
{
    __shared__ unsigned ebuf[8*512];     // 16KB only
    int b = blockIdx.x >> 3, qb = blockIdx.x & 7;
    const float* Xx = xyz + b*3*NPT;
    const float* Xy = Xx + NPT;
    const float* Xz = Xx + 2*NPT;
    int wid = threadIdx.x>>5, lane = threadIdx.x&31;
    unsigned* wbuf = ebuf + wid*512;
    int wn = 0;
    for (int q=0;q<16;++q){
        int s = qb*128 + wid*16 + q;
        int ci = g_fps[b*NQ+s];
        float cx=__ldg(Xx+ci), cy=__ldg(Xy+ci), cz=__ldg(Xz+ci);
        unsigned gtag = (unsigned)(b*NQ+s) << 12;
        int cnt = 0;
        for (int bp=0;bp<NPT;bp+=32){
            int p = bp+lane;
            float dx=__ldg(Xx+p)-cx, dy=__ldg(Xy+p)-cy, dz=__ldg(Xz+p)-cz;
            float d2 = __fadd_rn(__fadd_rn(__fmul_rn(dx,dx),__fmul_rn(dy,dy)),__fmul_rn(dz,dz));
            bool in = (d2 <= 0.04f);   // reference excludes sqr > r^2
            unsigned mask = __ballot_sync(0xffffffffu, in);
            if (mask){
                int pc = __popc(mask);
                int take = min(pc, NSAMP-cnt);
                if (in){
                    int pos = __popc(mask & ((1u<<lane)-1u));
                    if (pos < take) wbuf[wn+pos] = gtag | (unsigned)p;
                }
                wn += take; cnt += take;
                if (cnt >= NSAMP) break;
            }
        }
    }
    int gb = 0;
    if (lane==0) gb = atomicAdd(&g_ecnt, wn);
    gb = __shfl_sync(0xffffffffu, gb, 0);
    for (int i=lane;i<wn;i+=32) g_ent[gb+i] = wbuf[i];
}

// ---------------- fused 3-layer MLP on compacted entries + max scatter ---
// SMEM: activations only (34.5KB). Weights stream from L1 via __ldg.
__global__ void __launch_bounds__(256,2) mlp_kernel(const float* __restrict__ xyz,
                                                    const float* __restrict__ pts,
                                                    const float* __restrict__ out1,
                                                    float* __restrict__ out2)
{
    extern __shared__ float sm[];
    float* sX  = sm;            // 67*64 = 4288
    float* sH  = sm + 4288;     // 64*64 = 4096
    float* sB0 = sm + 8384;     // 64
    float* sB1 = sm + 8448;     // 64
    float* sB2 = sm + 8512;     // 128  (total 8640 floats = 34560 B)
    int t = threadIdx.x;
    if (t<64){ sB0[t]=g_B0[t]; sB1[t]=g_B1[t]; }
    if (t<128) sB2[t]=g_B2[t];
    int E = g_ecnt;
    int tiles = (E+63)>>6;
    int tx = t&15, ty = t>>4;
    int* outI = (int*)out2;
    int le = t>>2, sub = t&3;
    for (int tb = blockIdx.x; tb < tiles; tb += gridDim.x){
        int tbase = tb<<6;
        __syncthreads();                       // prev tile done reading sX/sH
        {   // gather 67-channel input for 64 entries (4 threads / entry)
            int ge = tbase + le;
            unsigned raw = g_ent[ge < E ? ge : 0] & 0x3FFFFFFu;
            int p = raw & 4095; int g = raw >> 12; int bb = g >> 10, s = g & 1023;
            const float* pc = pts  + (size_t)(bb*64)*NPT + p;
            const float* xc = xyz  + (size_t)(bb*3)*NPT + p;
            const float* cc = out1 + bb*3*NQ + s;
            for (int c=sub;c<67;c+=4){
                float v;
                if (c<3) v = __ldg(xc + c*NPT) - __ldg(cc + c*NQ);
                else     v = __ldg(pc + (c-3)*NPT);
                sX[c*64+le] = v;
            }
        }
        __syncthreads();
        // ---- layer 0: 67 -> 64 ----
        float acc[4][4];
        #pragma unroll
        for (int j=0;j<4;j++){ float bb=sB0[ty*4+j];
            #pragma unroll
            for (int i=0;i<4;i++) acc[i][j]=bb; }
        #pragma unroll 4
        for (int k=0;k<67;k++){
            float4 xv = *(const float4*)&sX[k*64+tx*4];
            float4 wv = __ldg((const float4*)&g_W0[k*64+ty*4]);
            float xr[4]={xv.x,xv.y,xv.z,xv.w};
            float wr[4]={wv.x,wv.y,wv.z,wv.w};
            #pragma unroll
            for (int i=0;i<4;i++)
                #pragma unroll
                for (int j=0;j<4;j++) acc[i][j] = fmaf(xr[i],wr[j],acc[i][j]);
        }
        #pragma unroll
        for (int j=0;j<4;j++){
            float4 hv = make_float4(fmaxf(acc[0][j],0.f),fmaxf(acc[1][j],0.f),
                                    fmaxf(acc[2][j],0.f),fmaxf(acc[3][j],0.f));
            *(float4*)&sH[(ty*4+j)*64 + tx*4] = hv;
        }
        __syncthreads();
        // ---- layer 1: 64 -> 64 (reads sH, writes sX) ----
        #pragma unroll
        for (int j=0;j<4;j++){ float bb=sB1[ty*4+j];
            #pragma unroll
            for (int i=0;i<4;i++) acc[i][j]=bb; }
        #pragma unroll 4
        for (int k=0;k<64;k++){
            float4 xv = *(const float4*)&sH[k*64+tx*4];
            float4 wv = __ldg((const float4*)&g_W1[k*64+ty*4]);
            float xr[4]={xv.x,xv.y,xv.z,xv.w};
            float wr[4]={wv.x,wv.y,wv.z,wv.w};
            #pragma unroll
            for (int i=0;i<4;i++)
                #pragma unroll
                for (int j=0;j<4;j++) acc[i][j] = fmaf(xr[i],wr[j],acc[i][j]);
        }
        #pragma unroll
        for (int j=0;j<4;j++){
            float4 hv = make_float4(fmaxf(acc[0][j],0.f),fmaxf(acc[1][j],0.f),
                                    fmaxf(acc[2][j],0.f),fmaxf(acc[3][j],0.f));
            *(float4*)&sX[(ty*4+j)*64 + tx*4] = hv;
        }
        __syncthreads();
        // ---- layer 2: 64 -> 128 + relu + atomicMax scatter ----
        float a2[4][8];
        #pragma unroll
        for (int j=0;j<8;j++){ float bb=sB2[ty*8+j];
            #pragma unroll
            for (int i=0;i<4;i++) a2[i][j]=bb; }
        #pragma unroll 2
        for (int k=0;k<64;k++){
            float4 xv = *(const float4*)&sX[k*64+tx*4];
            float4 wa = __ldg((const float4*)&g_W2[k*128+ty*8]);
            float4 wb = __ldg((const float4*)&g_W2[k*128+ty*8+4]);
            float xr[4]={xv.x,xv.y,xv.z,xv.w};
            float wr[8]={wa.x,wa.y,wa.z,wa.w,wb.x,wb.y,wb.z,wb.w};
            #pragma unroll
            for (int i=0;i<4;i++)
                #pragma unroll
                for (int j=0;j<8;j++) a2[i][j]=fmaf(xr[i],wr[j],a2[i][j]);
        }
        #pragma unroll
        for (int i=0;i<4;i++){
            int ge = tbase + tx*4 + i;
            if (ge < E){
                unsigned raw = g_ent[ge] & 0x3FFFFFFu;
                int g = raw >> 12; int bb = g >> 10, s = g & 1023;
                int* po = outI + (bb*128 + ty*8)*NQ + s;
                #pragma unroll
                for (int j=0;j<8;j++)
                    atomicMax(po + j*NQ, __float_as_int(fmaxf(a2[i][j],0.f)));
            }
        }
    }
}

extern "C" void kernel_launch(void* const* d_in, const int* in_sizes, int n_in,
                              void* d_out, int out_size)
{
    const float* xyz = (const float*)d_in[0];
    const float* pts = (const float*)d_in[1];
    float* out1 = (float*)d_out;
    float* out2 = out1 + OUT1SZ;

    prep_kernel<<<2048,256>>>(out2,
        (const float*)d_in[2],(const float*)d_in[3],(const float*)d_in[4],
        (const float*)d_in[5],(const float*)d_in[6],(const float*)d_in[7],
        (const float*)d_in[8],(const float*)d_in[9],(const float*)d_in[10],
        (const float*)d_in[11],(const float*)d_in[12],(const float*)d_in[13],
        (const float*)d_in[14],(const float*)d_in[15],(const float*)d_in[16],
        (const float*)d_in[17],(const float*)d_in[18],(const float*)d_in[19]);
    fps_kernel<<<16,1024>>>(xyz);
    gather_kernel<<<192,256>>>(out1, xyz);
    bq_kernel<<<128,256>>>(xyz);
    mlp_kernel<<<296,256,34560>>>(xyz, pts, out1, out2);
}